// round 1
// baseline (speedup 1.0000x reference)
#include <cuda_runtime.h>
#include <cuda_bf16.h>
#include <math.h>

// ---------------- problem constants ----------------
#define BB   2
#define TT   4096
#define HH   8
#define EE   64
#define MM   256
#define NHSH 4
#define BHN  16            // B*H
#define BHT  (BHN*TT)      // 65536
#define NB   32            // buckets per (hash, bh)
#define BS   128           // bucket size

#define TEMP   0.125f                 // 1/sqrt(64)
#define DN     0.3535533905932738f    // sqrt(TEMP)
#define RATIO  0.0625f                // 256^-0.5

// ---------------- scratch (device globals; no runtime alloc) ----------------
__device__ float g_q[BHT*EE];
__device__ float g_k[BHT*EE];
__device__ float g_v[BHT*EE];
__device__ float g_qn2[BHT], g_kn2[BHT];
__device__ float g_MQ2[BHN], g_MK2[BHN];
__device__ unsigned long long g_qkeys[NHSH*BHT];
__device__ unsigned long long g_kkeys[NHSH*BHT];
__device__ int g_qpos[NHSH*BHT], g_kpos[NHSH*BHT];
__device__ int g_qrev[NHSH*BHT], g_krev[NHSH*BHT];
__device__ float g_qp[BHT*MM];         // q_prime
__device__ float g_kp[BHT*MM];         // k logv then k_prime
__device__ float g_qls[BHT];           // per-row q stabilizer
__device__ float g_krowmax[BHT];
__device__ float g_kls[BHN];           // per-bh k stabilizer
__device__ float g_kv[BHN*MM*EE];
__device__ float g_ksum[BHN*MM];
__device__ float g_qkv[BHT*EE];
__device__ float g_qk1[BHT];
__device__ float g_o[NHSH*BHT*EE];     // per-hash bucket outputs (scattered)
__device__ float g_logits[NHSH*BHT];
__device__ float g_dsum[NHSH*BHT];

// ---------------- helpers ----------------
__device__ __forceinline__ unsigned f2sortable(float f) {
    unsigned u = __float_as_uint(f);
    return (u & 0x80000000u) ? ~u : (u | 0x80000000u);
}

// ---------------- K0: transpose (B,T,H,E)->(bh,T,E) + row norms ----------------
__global__ void k_transpose(const float* __restrict__ q, const float* __restrict__ k,
                            const float* __restrict__ v) {
    __shared__ float sred[8][2];
    int tid = threadIdx.x;
    int g = tid >> 6;          // 0..3 rows per block
    int e = tid & 63;
    int row = blockIdx.x * 4 + g;
    int bh = row >> 12;
    int t  = row & 4095;
    int b = bh >> 3, h = bh & 7;
    int src = ((b * TT + t) * HH + h) * EE + e;
    float qv = q[src], kv2 = k[src], vv = v[src];
    g_q[row*EE+e] = qv; g_k[row*EE+e] = kv2; g_v[row*EE+e] = vv;
    float sq = qv*qv, sk = kv2*kv2;
    #pragma unroll
    for (int m = 16; m > 0; m >>= 1) {
        sq += __shfl_xor_sync(0xffffffffu, sq, m);
        sk += __shfl_xor_sync(0xffffffffu, sk, m);
    }
    int w = tid >> 5;
    if ((tid & 31) == 0) { sred[w][0] = sq; sred[w][1] = sk; }
    __syncthreads();
    if (e == 0) {
        g_qn2[row] = sred[2*g][0] + sred[2*g+1][0];
        g_kn2[row] = sred[2*g][1] + sred[2*g+1][1];
    }
}

// ---------------- K1: per-bh max of squared norms ----------------
__global__ void k_maxnorm() {
    __shared__ float s[8][2];
    int bh = blockIdx.x, tid = threadIdx.x;
    float mq = 0.f, mk = 0.f;
    for (int t = tid; t < TT; t += 256) {
        mq = fmaxf(mq, g_qn2[bh*TT+t]);
        mk = fmaxf(mk, g_kn2[bh*TT+t]);
    }
    #pragma unroll
    for (int m = 16; m > 0; m >>= 1) {
        mq = fmaxf(mq, __shfl_xor_sync(0xffffffffu, mq, m));
        mk = fmaxf(mk, __shfl_xor_sync(0xffffffffu, mk, m));
    }
    if ((tid & 31) == 0) { s[tid>>5][0] = mq; s[tid>>5][1] = mk; }
    __syncthreads();
    if (tid == 0) {
        float a = s[0][0], b2 = s[0][1];
        for (int i = 1; i < 8; i++) { a = fmaxf(a, s[i][0]); b2 = fmaxf(b2, s[i][1]); }
        g_MQ2[bh] = a; g_MK2[bh] = b2;
    }
}

// ---------------- K2: LSH hash keys (packed sortable key | index) ----------------
__global__ void k_hash(const float* __restrict__ alpha, const float* __restrict__ beta) {
    int w = threadIdx.x >> 5, lane = threadIdx.x & 31;
    int row = blockIdx.x * 8 + w;
    int bh = row >> 12, t = row & 4095;
    float aq[NHSH] = {0,0,0,0}, ak[NHSH] = {0,0,0,0};
    for (int e = lane; e < EE; e += 32) {
        float xq = g_q[row*EE+e], xk = g_k[row*EE+e];
        #pragma unroll
        for (int h = 0; h < NHSH; h++) {
            float al = alpha[e*NHSH+h];
            aq[h] = fmaf(xq, al, aq[h]);
            ak[h] = fmaf(xk, al, ak[h]);
        }
    }
    #pragma unroll
    for (int m = 16; m > 0; m >>= 1) {
        #pragma unroll
        for (int h = 0; h < NHSH; h++) {
            aq[h] += __shfl_xor_sync(0xffffffffu, aq[h], m);
            ak[h] += __shfl_xor_sync(0xffffffffu, ak[h], m);
        }
    }
    if (lane == 0) {
        float s2 = g_MQ2[bh] + g_MK2[bh];
        float extq = sqrtf(fmaxf(s2 - g_qn2[row], 0.f));
        float extk = sqrtf(fmaxf(s2 - g_kn2[row], 0.f));
        #pragma unroll
        for (int h = 0; h < NHSH; h++) {
            float hq = aq[h] + extq * alpha[64*NHSH+h] + beta[h];
            float hk = ak[h] + extk * alpha[65*NHSH+h] + beta[h];
            g_qkeys[(h*BHN+bh)*TT + t] = (((unsigned long long)f2sortable(hq)) << 32) | (unsigned)t;
            g_kkeys[(h*BHN+bh)*TT + t] = (((unsigned long long)f2sortable(hk)) << 32) | (unsigned)t;
        }
    }
}

// ---------------- K3: bitonic argsort (stable via packed index) ----------------
__global__ void k_sort() {
    __shared__ unsigned long long s[TT];
    int which = blockIdx.x >> 6;                 // 0 = q, 1 = k
    int hb = blockIdx.x & 63;
    const unsigned long long* src = which ? g_kkeys : g_qkeys;
    int* pos = which ? g_kpos : g_qpos;
    int* rev = which ? g_krev : g_qrev;
    int base = hb * TT;
    for (int i = threadIdx.x; i < TT; i += 512) s[i] = src[base+i];
    for (int k2 = 2; k2 <= TT; k2 <<= 1) {
        for (int j = k2 >> 1; j > 0; j >>= 1) {
            __syncthreads();
            for (int i = threadIdx.x; i < TT; i += 512) {
                int ixj = i ^ j;
                if (ixj > i) {
                    unsigned long long a = s[i], b = s[ixj];
                    bool asc = ((i & k2) == 0);
                    if ((a > b) == asc) { s[i] = b; s[ixj] = a; }
                }
            }
        }
    }
    __syncthreads();
    for (int i = threadIdx.x; i < TT; i += 512) {
        int orig = (int)(s[i] & 0xffffffffu);
        pos[base+i] = orig;
        rev[base+orig] = i;
    }
}

// ---------------- K4: q Performer features (per-row stabilizer) ----------------
__global__ void k_feats_q(const float* __restrict__ proj) {
    extern __shared__ float sm[];
    float* qrow = sm;       // 64
    float* red  = sm + 64;  // 9
    int tid = threadIdx.x;
    float pcol[EE];
    const float4* p4 = (const float4*)(proj + tid*EE);
    #pragma unroll
    for (int i = 0; i < 16; i++) {
        float4 w = p4[i];
        pcol[4*i] = w.x; pcol[4*i+1] = w.y; pcol[4*i+2] = w.z; pcol[4*i+3] = w.w;
    }
    int row0 = blockIdx.x * 16;
    for (int r = 0; r < 16; r++) {
        int row = row0 + r;
        if (tid < 64) qrow[tid] = g_q[row*EE+tid];
        __syncthreads();
        float dot = 0.f;
        #pragma unroll
        for (int e = 0; e < EE; e++) dot = fmaf(qrow[e], pcol[e], dot);
        float logv = DN * dot - 0.0625f * g_qn2[row];   // 0.5*dn^2 = 0.0625
        float mx = logv;
        #pragma unroll
        for (int m = 16; m > 0; m >>= 1) mx = fmaxf(mx, __shfl_xor_sync(0xffffffffu, mx, m));
        if ((tid & 31) == 0) red[tid>>5] = mx;
        __syncthreads();
        if (tid == 0) {
            float a = red[0];
            for (int i = 1; i < 8; i++) a = fmaxf(a, red[i]);
            red[8] = a;
        }
        __syncthreads();
        float stab = red[8];
        g_qp[row*MM+tid] = expf(logv - stab) * RATIO;
        if (tid == 0) g_qls[row] = stab;
        __syncthreads();
    }
}

// ---------------- K5: k features pass1 (logv + row max) ----------------
__global__ void k_feats_k(const float* __restrict__ proj) {
    extern __shared__ float sm[];
    float* krow = sm;
    float* red  = sm + 64;
    int tid = threadIdx.x;
    float pcol[EE];
    const float4* p4 = (const float4*)(proj + tid*EE);
    #pragma unroll
    for (int i = 0; i < 16; i++) {
        float4 w = p4[i];
        pcol[4*i] = w.x; pcol[4*i+1] = w.y; pcol[4*i+2] = w.z; pcol[4*i+3] = w.w;
    }
    int row0 = blockIdx.x * 16;
    for (int r = 0; r < 16; r++) {
        int row = row0 + r;
        if (tid < 64) krow[tid] = g_k[row*EE+tid];
        __syncthreads();
        float dot = 0.f;
        #pragma unroll
        for (int e = 0; e < EE; e++) dot = fmaf(krow[e], pcol[e], dot);
        float logv = DN * dot - 0.0625f * g_kn2[row];
        float mx = logv;
        #pragma unroll
        for (int m = 16; m > 0; m >>= 1) mx = fmaxf(mx, __shfl_xor_sync(0xffffffffu, mx, m));
        if ((tid & 31) == 0) red[tid>>5] = mx;
        __syncthreads();
        if (tid == 0) {
            float a = red[0];
            for (int i = 1; i < 8; i++) a = fmaxf(a, red[i]);
            red[8] = a;
        }
        __syncthreads();
        g_kp[row*MM+tid] = logv;
        if (tid == 0) g_krowmax[row] = red[8];
        __syncthreads();
    }
}

// ---------------- K6: per-bh k stabilizer ----------------
__global__ void k_kls() {
    __shared__ float s[8];
    int bh = blockIdx.x, tid = threadIdx.x;
    float m = -3.402823466e38f;
    for (int t = tid; t < TT; t += 256) m = fmaxf(m, g_krowmax[bh*TT+t]);
    #pragma unroll
    for (int mm = 16; mm > 0; mm >>= 1) m = fmaxf(m, __shfl_xor_sync(0xffffffffu, m, mm));
    if ((tid & 31) == 0) s[tid>>5] = m;
    __syncthreads();
    if (tid == 0) {
        float a = s[0];
        for (int i = 1; i < 8; i++) a = fmaxf(a, s[i]);
        g_kls[bh] = a;
    }
}

// ---------------- K7: k_prime = exp(logv - kls)*ratio ----------------
__global__ void k_kexp() {
    int idx4 = blockIdx.x * 256 + threadIdx.x;      // float4 index
    int bh = idx4 >> 18;                            // (4096*256)/4 = 2^18 per bh
    float kls = g_kls[bh];
    float4* p = (float4*)g_kp;
    float4 x = p[idx4];
    x.x = expf(x.x - kls) * RATIO;
    x.y = expf(x.y - kls) * RATIO;
    x.z = expf(x.z - kls) * RATIO;
    x.w = expf(x.w - kls) * RATIO;
    p[idx4] = x;
}

// ---------------- K8: zero kv/ksum ----------------
__global__ void k_zero() {
    int i = blockIdx.x * 256 + threadIdx.x;
    if (i < BHN*MM*EE) g_kv[i] = 0.f;
    if (i < BHN*MM) g_ksum[i] = 0.f;
}

// ---------------- K9: kv = k_prime^T @ v, ksum = sum_s k_prime ----------------
__global__ void k_kvker() {
    __shared__ float vs[128*EE];
    int bh = blockIdx.y, sc = blockIdx.x, tid = threadIdx.x;
    int s0 = sc * 128;
    for (int i = tid; i < 128*EE; i += 256) vs[i] = g_v[(bh*TT+s0)*EE + i];
    __syncthreads();
    float acc[EE];
    #pragma unroll
    for (int d = 0; d < EE; d++) acc[d] = 0.f;
    float asum = 0.f;
    int m = tid;
    const float* kp = g_kp + ((size_t)(bh*TT+s0))*MM + m;
    for (int s = 0; s < 128; s++) {
        float kpv = kp[(size_t)s*MM];
        asum += kpv;
        #pragma unroll
        for (int d = 0; d < EE; d++) acc[d] = fmaf(kpv, vs[s*EE+d], acc[d]);
    }
    float* kvp = g_kv + (bh*MM+m)*EE;
    #pragma unroll
    for (int d = 0; d < EE; d++) atomicAdd(kvp + d, acc[d]);
    atomicAdd(g_ksum + bh*MM+m, asum);
}

// ---------------- K10: qkv = q_prime @ kv ----------------
__global__ void k_qkvker() {
    extern __shared__ float kvs[];   // 16384
    int tid = threadIdx.x;
    int bh = blockIdx.x >> 8;        // 256 blocks per bh
    int t0 = (blockIdx.x & 255) * 16;
    for (int i = tid; i < MM*EE; i += 256) kvs[i] = g_kv[bh*MM*EE + i];
    __syncthreads();
    int dl = tid & 63, tl = tid >> 6;
    for (int rb = 0; rb < 4; rb++) {
        int row = bh*TT + t0 + rb*4 + tl;
        const float* qp = g_qp + (size_t)row*MM;
        float acc = 0.f;
        #pragma unroll 8
        for (int m = 0; m < MM; m++) acc = fmaf(qp[m], kvs[m*EE+dl], acc);
        g_qkv[row*EE+dl] = acc;
    }
}

// ---------------- K11: qk1 = q_prime . ksum ----------------
__global__ void k_qk1ker() {
    int w = threadIdx.x >> 5, lane = threadIdx.x & 31;
    int row = blockIdx.x * 8 + w;
    int bh = row >> 12;
    const float* qp = g_qp + (size_t)row*MM;
    const float* ks = g_ksum + bh*MM;
    float a = 0.f;
    for (int m = lane; m < MM; m += 32) a = fmaf(qp[m], ks[m], a);
    #pragma unroll
    for (int m = 16; m > 0; m >>= 1) a += __shfl_xor_sync(0xffffffffu, a, m);
    if (lane == 0) g_qk1[row] = a;
}

// ---------------- K12: per-bucket attention (the heavy kernel) ----------------
// smem float layout:
//  [0,8320)      sq     128x(64+1)
//  [8320,16640)  sqp    128x(64+1)  (chunked)
//  [16640,24960) sk
//  [24960,33280) skp    (chunked)
//  [33280,41600) sv
//  dots overlays [0,16640): 128 x pitch 130
//  tail: qi 41600, ki 41728, qb 41856, kb 41984, pls 42112  (42240 floats total)
__global__ void __launch_bounds__(256, 1) k_bucket() {
    extern __shared__ float sm[];
    float* sq  = sm;
    float* sqp = sm + 8320;
    float* sk  = sm + 16640;
    float* skp = sm + 24960;
    float* sv  = sm + 33280;
    float* dots = sm;                       // pitch 130, overlays sq+sqp
    int*      qi = (int*)(sm + 41600);
    int*      ki = (int*)(sm + 41728);
    unsigned* qb = (unsigned*)(sm + 41856);
    unsigned* kb = (unsigned*)(sm + 41984);
    float*   pls = sm + 42112;

    int tid = threadIdx.x;
    int n  = blockIdx.x & 31;
    int bh = (blockIdx.x >> 5) & 15;
    int h  = blockIdx.x >> 9;
    int hb = h * BHN + bh;

    if (tid < 128) qi[tid] = g_qpos[hb*TT + n*128 + tid];
    else           ki[tid-128] = g_kpos[hb*TT + n*128 + (tid-128)];
    __syncthreads();

    for (int idx = tid; idx < 128*EE; idx += 256) {
        int r = idx >> 6, e = idx & 63;
        sq[r*65+e] = g_q[(bh*TT+qi[r])*EE + e];
        sk[r*65+e] = g_k[(bh*TT+ki[r])*EE + e];
        sv[r*65+e] = g_v[(bh*TT+ki[r])*EE + e];
    }
    if (tid < 128) {
        int q0 = qi[tid];
        unsigned pb = 0;
        #pragma unroll
        for (int hh = 0; hh < NHSH; hh++)
            pb |= ((unsigned)(g_qrev[(hh*BHN+bh)*TT + q0] >> 7)) << (8*hh);
        qb[tid] = pb;
        pls[tid] = g_qls[bh*TT + q0] + g_kls[bh];
    } else {
        int j = tid - 128;
        int k0 = ki[j];
        unsigned pb = 0;
        #pragma unroll
        for (int hh = 0; hh < NHSH; hh++)
            pb |= ((unsigned)(g_krev[(hh*BHN+bh)*TT + k0] >> 7)) << (8*hh);
        kb[j] = pb;
    }
    __syncthreads();

    int tx = tid & 15, ty = tid >> 4;
    float accI[8][8], accP[8][8];
    #pragma unroll
    for (int i = 0; i < 8; i++)
        #pragma unroll
        for (int j = 0; j < 8; j++) { accI[i][j] = 0.f; accP[i][j] = 0.f; }

    // inner = s_q @ s_k^T (K=64)
    for (int e = 0; e < 64; e++) {
        float a[8], b[8];
        #pragma unroll
        for (int i = 0; i < 8; i++) a[i] = sq[(ty*8+i)*65 + e];
        #pragma unroll
        for (int j = 0; j < 8; j++) b[j] = sk[(tx*8+j)*65 + e];
        #pragma unroll
        for (int i = 0; i < 8; i++)
            #pragma unroll
            for (int j = 0; j < 8; j++)
                accI[i][j] = fmaf(a[i], b[j], accI[i][j]);
    }

    // dots_prime = sq_p @ sk_p^T (K=256, chunked by 64)
    for (int c = 0; c < 4; c++) {
        __syncthreads();
        for (int idx = tid; idx < 128*64; idx += 256) {
            int r = idx >> 6, mm = idx & 63;
            sqp[r*65+mm] = g_qp[((size_t)(bh*TT+qi[r]))*MM + c*64 + mm];
            skp[r*65+mm] = g_kp[((size_t)(bh*TT+ki[r]))*MM + c*64 + mm];
        }
        __syncthreads();
        for (int mm = 0; mm < 64; mm++) {
            float a[8], b[8];
            #pragma unroll
            for (int i = 0; i < 8; i++) a[i] = sqp[(ty*8+i)*65 + mm];
            #pragma unroll
            for (int j = 0; j < 8; j++) b[j] = skp[(tx*8+j)*65 + mm];
            #pragma unroll
            for (int i = 0; i < 8; i++)
                #pragma unroll
                for (int j = 0; j < 8; j++)
                    accP[i][j] = fmaf(a[i], b[j], accP[i][j]);
        }
    }
    __syncthreads();   // all smem reads of sq/sqp done; dots may now overlay

    const float LOGT[5] = {0.f, 0.f, 0.69314718056f, 1.09861228867f, 1.38629436112f};
    const float RCPT[5] = {1.f, 1.f, 0.5f, 0.33333333333f, 0.25f};
    unsigned qb_r[8], kb_c[8];
    float plsr[8], rowm[8];
    #pragma unroll
    for (int i = 0; i < 8; i++) { qb_r[i] = qb[ty*8+i]; plsr[i] = pls[ty*8+i]; rowm[i] = -3.402823466e38f; }
    #pragma unroll
    for (int j = 0; j < 8; j++) kb_c[j] = kb[tx*8+j];

    #pragma unroll
    for (int i = 0; i < 8; i++)
        #pragma unroll
        for (int j = 0; j < 8; j++) {
            int cnt = __popc(__vcmpeq4(qb_r[i], kb_c[j])) >> 3;
            float inner = accI[i][j] * TEMP - LOGT[cnt];
            accI[i][j] = inner;
            accP[i][j] *= RCPT[cnt];
            rowm[i] = fmaxf(rowm[i], inner);
        }
    #pragma unroll
    for (int i = 0; i < 8; i++)
        #pragma unroll
        for (int m = 8; m >= 1; m >>= 1)
            rowm[i] = fmaxf(rowm[i], __shfl_xor_sync(0xffffffffu, rowm[i], m));

    #pragma unroll
    for (int i = 0; i < 8; i++) {
        float l = fmaxf(rowm[i], plsr[i]);
        float e2 = expf(plsr[i] - l);
        float s = 0.f;
        #pragma unroll
        for (int j = 0; j < 8; j++) {
            float d = expf(accI[i][j] - l) - accP[i][j] * e2;
            s += d;
            dots[(ty*8+i)*130 + tx*8 + j] = d;
        }
        #pragma unroll
        for (int m = 8; m >= 1; m >>= 1) s += __shfl_xor_sync(0xffffffffu, s, m);
        if (tx == 0) {
            int q0 = qi[ty*8+i];
            g_logits[hb*TT + q0] = l;
            g_dsum[hb*TT + q0]   = s;
        }
    }
    __syncthreads();

    // epilogue: so = dots @ s_v
    float acc2[8][4];
    #pragma unroll
    for (int i = 0; i < 8; i++)
        #pragma unroll
        for (int dd = 0; dd < 4; dd++) acc2[i][dd] = 0.f;
    for (int j = 0; j < 128; j++) {
        float vv[4];
        #pragma unroll
        for (int dd = 0; dd < 4; dd++) vv[dd] = sv[j*65 + tx*4 + dd];
        #pragma unroll
        for (int i = 0; i < 8; i++) {
            float dij = dots[(ty*8+i)*130 + j];
            #pragma unroll
            for (int dd = 0; dd < 4; dd++) acc2[i][dd] = fmaf(dij, vv[dd], acc2[i][dd]);
        }
    }
    #pragma unroll
    for (int i = 0; i < 8; i++) {
        int q0 = qi[ty*8+i];
        float* op = g_o + ((size_t)(hb*TT + q0))*EE + tx*4;
        #pragma unroll
        for (int dd = 0; dd < 4; dd++) op[dd] = acc2[i][dd];
    }
}

// ---------------- K13: combine across hashes + global correction ----------------
__global__ void k_combine(float* __restrict__ out) {
    int tid = threadIdx.x;
    int row = blockIdx.x * 4 + (tid >> 6);
    int d = tid & 63;
    int bh = row >> 12, t = row & 4095;
    float l[NHSH];
    #pragma unroll
    for (int h = 0; h < NHSH; h++) l[h] = g_logits[(h*BHN+bh)*TT + t];
    float mx = fmaxf(fmaxf(l[0], l[1]), fmaxf(l[2], l[3]));
    float se = 0.f;
    #pragma unroll
    for (int h = 0; h < NHSH; h++) se += expf(l[h] - mx);
    float nls = mx + logf(se);
    float o = 0.f, nr = 0.f;
    #pragma unroll
    for (int h = 0; h < NHSH; h++) {
        float p = expf(l[h] - nls);
        o  = fmaf(g_o[((size_t)((h*BHN+bh)*TT + t))*EE + d], p, o);
        nr = fmaf(g_dsum[(h*BHN+bh)*TT + t], p, nr);
    }
    float ps = expf(g_qls[row] + g_kls[bh] - nls);
    o  = fmaf(g_qkv[row*EE+d], ps, o);
    nr = fmaf(g_qk1[row], ps, nr);
    o /= fmaxf(nr, 1e-6f);
    int b = bh >> 3, hh = bh & 7;
    out[((b*TT + t)*HH + hh)*EE + d] = o;
}

// ---------------- launch ----------------
extern "C" void kernel_launch(void* const* d_in, const int* in_sizes, int n_in,
                              void* d_out, int out_size) {
    const float* q     = (const float*)d_in[0];
    const float* k     = (const float*)d_in[1];
    const float* v     = (const float*)d_in[2];
    const float* proj  = (const float*)d_in[3];
    const float* alpha = (const float*)d_in[4];
    const float* beta  = (const float*)d_in[5];
    float* out = (float*)d_out;

    cudaFuncSetAttribute(k_feats_q, cudaFuncAttributeMaxDynamicSharedMemorySize, (64+9)*4);
    cudaFuncSetAttribute(k_feats_k, cudaFuncAttributeMaxDynamicSharedMemorySize, (64+9)*4);
    cudaFuncSetAttribute(k_qkvker,  cudaFuncAttributeMaxDynamicSharedMemorySize, MM*EE*4);
    cudaFuncSetAttribute(k_bucket,  cudaFuncAttributeMaxDynamicSharedMemorySize, 42240*4);

    k_transpose<<<BHT/4, 256>>>(q, k, v);
    k_maxnorm<<<BHN, 256>>>();
    k_hash<<<BHT/8, 256>>>(alpha, beta);
    k_sort<<<2*NHSH*BHN, 512>>>();
    k_feats_q<<<BHT/16, 256, (64+9)*4>>>(proj);
    k_feats_k<<<BHT/16, 256, (64+9)*4>>>(proj);
    k_kls<<<BHN, 256>>>();
    k_kexp<<<(BHT*MM/4)/256, 256>>>();
    k_zero<<<(BHN*MM*EE + 255)/256, 256>>>();
    k_kvker<<<dim3(TT/128, BHN), 256>>>();
    k_qkvker<<<BHT/16, 256, MM*EE*4>>>();
    k_qk1ker<<<BHT/8, 256>>>();
    k_bucket<<<NHSH*BHN*NB, 256, 42240*4>>>();
    k_combine<<<BHT/4, 256>>>(out);
}

// round 3
// speedup vs baseline: 1.9061x; 1.9061x over previous
#include <cuda_runtime.h>
#include <cuda_bf16.h>
#include <math.h>

// ---------------- problem constants ----------------
#define BB   2
#define TT   4096
#define HH   8
#define EE   64
#define MM   256
#define NHSH 4
#define BHN  16            // B*H
#define BHT  (BHN*TT)      // 65536
#define NB   32            // buckets per (hash, bh)
#define BS   128           // bucket size

#define TEMP   0.125f                 // 1/sqrt(64)
#define DN     0.3535533905932738f    // sqrt(TEMP)
#define RATIO  0.0625f                // 256^-0.5

// ---------------- scratch (device globals; no runtime alloc) ----------------
__device__ float g_q[BHT*EE];
__device__ float g_k[BHT*EE];
__device__ float g_v[BHT*EE];
__device__ float g_qn2[BHT], g_kn2[BHT];
__device__ float g_MQ2[BHN], g_MK2[BHN];
__device__ unsigned long long g_qkeys[NHSH*BHT];
__device__ unsigned long long g_kkeys[NHSH*BHT];
__device__ int g_qpos[NHSH*BHT], g_kpos[NHSH*BHT];
__device__ int g_qrev[NHSH*BHT], g_krev[NHSH*BHT];
__device__ float g_qp[BHT*MM];         // q_prime
__device__ float g_kp[BHT*MM];         // k logv then k_prime
__device__ float g_qls[BHT];           // per-row q stabilizer
__device__ float g_krowmax[BHT];
__device__ float g_kls[BHN];           // per-bh k stabilizer
__device__ float g_kv[BHN*MM*EE];
__device__ float g_ksum[BHN*MM];
__device__ float g_qkv[BHT*EE];
__device__ float g_qk1[BHT];
__device__ float g_o[NHSH*BHT*EE];     // per-hash bucket outputs (scattered)
__device__ float g_logits[NHSH*BHT];
__device__ float g_dsum[NHSH*BHT];

// ---------------- helpers ----------------
__device__ __forceinline__ unsigned f2sortable(float f) {
    unsigned u = __float_as_uint(f);
    return (u & 0x80000000u) ? ~u : (u | 0x80000000u);
}

// 16B-group XOR swizzle: tile is [64 e][128 r] floats; r4 = r>>2 in 0..31
__device__ __forceinline__ int swz(int e, int r4) { return ((r4 ^ (e & 31)) << 2); }

// ---------------- K0: transpose (B,T,H,E)->(bh,T,E) + row norms ----------------
__global__ void k_transpose(const float* __restrict__ q, const float* __restrict__ k,
                            const float* __restrict__ v) {
    __shared__ float sred[8][2];
    int tid = threadIdx.x;
    int g = tid >> 6;          // 0..3 rows per block
    int e = tid & 63;
    int row = blockIdx.x * 4 + g;
    int bh = row >> 12;
    int t  = row & 4095;
    int b = bh >> 3, h = bh & 7;
    int src = ((b * TT + t) * HH + h) * EE + e;
    float qv = q[src], kv2 = k[src], vv = v[src];
    g_q[row*EE+e] = qv; g_k[row*EE+e] = kv2; g_v[row*EE+e] = vv;
    float sq = qv*qv, sk = kv2*kv2;
    #pragma unroll
    for (int m = 16; m > 0; m >>= 1) {
        sq += __shfl_xor_sync(0xffffffffu, sq, m);
        sk += __shfl_xor_sync(0xffffffffu, sk, m);
    }
    int w = tid >> 5;
    if ((tid & 31) == 0) { sred[w][0] = sq; sred[w][1] = sk; }
    __syncthreads();
    if (e == 0) {
        g_qn2[row] = sred[2*g][0] + sred[2*g+1][0];
        g_kn2[row] = sred[2*g][1] + sred[2*g+1][1];
    }
}

// ---------------- K1: per-bh max of squared norms ----------------
__global__ void k_maxnorm() {
    __shared__ float s[8][2];
    int bh = blockIdx.x, tid = threadIdx.x;
    float mq = 0.f, mk = 0.f;
    for (int t = tid; t < TT; t += 256) {
        mq = fmaxf(mq, g_qn2[bh*TT+t]);
        mk = fmaxf(mk, g_kn2[bh*TT+t]);
    }
    #pragma unroll
    for (int m = 16; m > 0; m >>= 1) {
        mq = fmaxf(mq, __shfl_xor_sync(0xffffffffu, mq, m));
        mk = fmaxf(mk, __shfl_xor_sync(0xffffffffu, mk, m));
    }
    if ((tid & 31) == 0) { s[tid>>5][0] = mq; s[tid>>5][1] = mk; }
    __syncthreads();
    if (tid == 0) {
        float a = s[0][0], b2 = s[0][1];
        for (int i = 1; i < 8; i++) { a = fmaxf(a, s[i][0]); b2 = fmaxf(b2, s[i][1]); }
        g_MQ2[bh] = a; g_MK2[bh] = b2;
    }
}

// ---------------- K2: LSH hash keys (packed sortable key | index) ----------------
__global__ void k_hash(const float* __restrict__ alpha, const float* __restrict__ beta) {
    int w = threadIdx.x >> 5, lane = threadIdx.x & 31;
    int row = blockIdx.x * 8 + w;
    int bh = row >> 12, t = row & 4095;
    float aq[NHSH] = {0,0,0,0}, ak[NHSH] = {0,0,0,0};
    for (int e = lane; e < EE; e += 32) {
        float xq = g_q[row*EE+e], xk = g_k[row*EE+e];
        #pragma unroll
        for (int h = 0; h < NHSH; h++) {
            float al = alpha[e*NHSH+h];
            aq[h] = fmaf(xq, al, aq[h]);
            ak[h] = fmaf(xk, al, ak[h]);
        }
    }
    #pragma unroll
    for (int m = 16; m > 0; m >>= 1) {
        #pragma unroll
        for (int h = 0; h < NHSH; h++) {
            aq[h] += __shfl_xor_sync(0xffffffffu, aq[h], m);
            ak[h] += __shfl_xor_sync(0xffffffffu, ak[h], m);
        }
    }
    if (lane == 0) {
        float s2 = g_MQ2[bh] + g_MK2[bh];
        float extq = sqrtf(fmaxf(s2 - g_qn2[row], 0.f));
        float extk = sqrtf(fmaxf(s2 - g_kn2[row], 0.f));
        #pragma unroll
        for (int h = 0; h < NHSH; h++) {
            float hq = aq[h] + extq * alpha[64*NHSH+h] + beta[h];
            float hk = ak[h] + extk * alpha[65*NHSH+h] + beta[h];
            g_qkeys[(h*BHN+bh)*TT + t] = (((unsigned long long)f2sortable(hq)) << 32) | (unsigned)t;
            g_kkeys[(h*BHN+bh)*TT + t] = (((unsigned long long)f2sortable(hk)) << 32) | (unsigned)t;
        }
    }
}

// ---------------- K3: bitonic argsort (stable via packed index) ----------------
__global__ void k_sort() {
    __shared__ unsigned long long s[TT];
    int which = blockIdx.x >> 6;                 // 0 = q, 1 = k
    int hb = blockIdx.x & 63;
    const unsigned long long* src = which ? g_kkeys : g_qkeys;
    int* pos = which ? g_kpos : g_qpos;
    int* rev = which ? g_krev : g_qrev;
    int base = hb * TT;
    for (int i = threadIdx.x; i < TT; i += 512) s[i] = src[base+i];
    for (int k2 = 2; k2 <= TT; k2 <<= 1) {
        for (int j = k2 >> 1; j > 0; j >>= 1) {
            __syncthreads();
            for (int i = threadIdx.x; i < TT; i += 512) {
                int ixj = i ^ j;
                if (ixj > i) {
                    unsigned long long a = s[i], b = s[ixj];
                    bool asc = ((i & k2) == 0);
                    if ((a > b) == asc) { s[i] = b; s[ixj] = a; }
                }
            }
        }
    }
    __syncthreads();
    for (int i = threadIdx.x; i < TT; i += 512) {
        int orig = (int)(s[i] & 0xffffffffu);
        pos[base+i] = orig;
        rev[base+orig] = i;
    }
}

// ---------------- K4: q Performer features (per-row stabilizer) ----------------
__global__ void k_feats_q(const float* __restrict__ proj) {
    extern __shared__ float sm[];
    float* qrow = sm;       // 64
    float* red  = sm + 64;  // 9
    int tid = threadIdx.x;
    float pcol[EE];
    const float4* p4 = (const float4*)(proj + tid*EE);
    #pragma unroll
    for (int i = 0; i < 16; i++) {
        float4 w = p4[i];
        pcol[4*i] = w.x; pcol[4*i+1] = w.y; pcol[4*i+2] = w.z; pcol[4*i+3] = w.w;
    }
    int row0 = blockIdx.x * 16;
    for (int r = 0; r < 16; r++) {
        int row = row0 + r;
        if (tid < 64) qrow[tid] = g_q[row*EE+tid];
        __syncthreads();
        float dot = 0.f;
        #pragma unroll
        for (int e = 0; e < EE; e++) dot = fmaf(qrow[e], pcol[e], dot);
        float logv = DN * dot - 0.0625f * g_qn2[row];   // 0.5*dn^2 = 0.0625
        float mx = logv;
        #pragma unroll
        for (int m = 16; m > 0; m >>= 1) mx = fmaxf(mx, __shfl_xor_sync(0xffffffffu, mx, m));
        if ((tid & 31) == 0) red[tid>>5] = mx;
        __syncthreads();
        if (tid == 0) {
            float a = red[0];
            for (int i = 1; i < 8; i++) a = fmaxf(a, red[i]);
            red[8] = a;
        }
        __syncthreads();
        float stab = red[8];
        g_qp[row*MM+tid] = expf(logv - stab) * RATIO;
        if (tid == 0) g_qls[row] = stab;
        __syncthreads();
    }
}

// ---------------- K5: k features pass1 (logv + row max) ----------------
__global__ void k_feats_k(const float* __restrict__ proj) {
    extern __shared__ float sm[];
    float* krow = sm;
    float* red  = sm + 64;
    int tid = threadIdx.x;
    float pcol[EE];
    const float4* p4 = (const float4*)(proj + tid*EE);
    #pragma unroll
    for (int i = 0; i < 16; i++) {
        float4 w = p4[i];
        pcol[4*i] = w.x; pcol[4*i+1] = w.y; pcol[4*i+2] = w.z; pcol[4*i+3] = w.w;
    }
    int row0 = blockIdx.x * 16;
    for (int r = 0; r < 16; r++) {
        int row = row0 + r;
        if (tid < 64) krow[tid] = g_k[row*EE+tid];
        __syncthreads();
        float dot = 0.f;
        #pragma unroll
        for (int e = 0; e < EE; e++) dot = fmaf(krow[e], pcol[e], dot);
        float logv = DN * dot - 0.0625f * g_kn2[row];
        float mx = logv;
        #pragma unroll
        for (int m = 16; m > 0; m >>= 1) mx = fmaxf(mx, __shfl_xor_sync(0xffffffffu, mx, m));
        if ((tid & 31) == 0) red[tid>>5] = mx;
        __syncthreads();
        if (tid == 0) {
            float a = red[0];
            for (int i = 1; i < 8; i++) a = fmaxf(a, red[i]);
            red[8] = a;
        }
        __syncthreads();
        g_kp[row*MM+tid] = logv;
        if (tid == 0) g_krowmax[row] = red[8];
        __syncthreads();
    }
}

// ---------------- K6: per-bh k stabilizer ----------------
__global__ void k_kls() {
    __shared__ float s[8];
    int bh = blockIdx.x, tid = threadIdx.x;
    float m = -3.402823466e38f;
    for (int t = tid; t < TT; t += 256) m = fmaxf(m, g_krowmax[bh*TT+t]);
    #pragma unroll
    for (int mm = 16; mm > 0; mm >>= 1) m = fmaxf(m, __shfl_xor_sync(0xffffffffu, m, mm));
    if ((tid & 31) == 0) s[tid>>5] = m;
    __syncthreads();
    if (tid == 0) {
        float a = s[0];
        for (int i = 1; i < 8; i++) a = fmaxf(a, s[i]);
        g_kls[bh] = a;
    }
}

// ---------------- K7: k_prime = exp(logv - kls)*ratio ----------------
__global__ void k_kexp() {
    int idx4 = blockIdx.x * 256 + threadIdx.x;      // float4 index
    int bh = idx4 >> 18;                            // (4096*256)/4 = 2^18 per bh
    float kls = g_kls[bh];
    float4* p = (float4*)g_kp;
    float4 x = p[idx4];
    x.x = expf(x.x - kls) * RATIO;
    x.y = expf(x.y - kls) * RATIO;
    x.z = expf(x.z - kls) * RATIO;
    x.w = expf(x.w - kls) * RATIO;
    p[idx4] = x;
}

// ---------------- K8: zero kv/ksum ----------------
__global__ void k_zero() {
    int i = blockIdx.x * 256 + threadIdx.x;
    if (i < BHN*MM*EE) g_kv[i] = 0.f;
    if (i < BHN*MM) g_ksum[i] = 0.f;
}

// ---------------- K9: kv = k_prime^T @ v, ksum = sum_s k_prime ----------------
__global__ void k_kvker() {
    __shared__ float vs[128*EE];
    int bh = blockIdx.y, sc = blockIdx.x, tid = threadIdx.x;
    int s0 = sc * 128;
    for (int i = tid; i < 128*EE; i += 256) vs[i] = g_v[(bh*TT+s0)*EE + i];
    __syncthreads();
    float acc[EE];
    #pragma unroll
    for (int d = 0; d < EE; d++) acc[d] = 0.f;
    float asum = 0.f;
    int m = tid;
    const float* kp = g_kp + ((size_t)(bh*TT+s0))*MM + m;
    for (int s = 0; s < 128; s++) {
        float kpv = kp[(size_t)s*MM];
        asum += kpv;
        #pragma unroll
        for (int d = 0; d < EE; d++) acc[d] = fmaf(kpv, vs[s*EE+d], acc[d]);
    }
    float* kvp = g_kv + (bh*MM+m)*EE;
    #pragma unroll
    for (int d = 0; d < EE; d++) atomicAdd(kvp + d, acc[d]);
    atomicAdd(g_ksum + bh*MM+m, asum);
}

// ---------------- K10: qkv = q_prime @ kv (kv transposed in smem, float4) ----------------
#define QKV_PITCH 260
__global__ void __launch_bounds__(256) k_qkvker() {
    extern __shared__ float kvT[];   // 64 * 260 floats
    int tid = threadIdx.x;
    int bh = blockIdx.x >> 5;        // 32 blocks per bh
    int t0 = (blockIdx.x & 31) * 128;
    // stage kv transposed: kvT[d][m]
    for (int idx = tid; idx < MM*16; idx += 256) {
        int m = idx >> 4, d4 = idx & 15;
        float4 w = *(const float4*)&g_kv[(bh*MM+m)*EE + d4*4];
        kvT[(d4*4+0)*QKV_PITCH+m] = w.x;
        kvT[(d4*4+1)*QKV_PITCH+m] = w.y;
        kvT[(d4*4+2)*QKV_PITCH+m] = w.z;
        kvT[(d4*4+3)*QKV_PITCH+m] = w.w;
    }
    __syncthreads();
    int dl = tid & 63, rg = tid >> 6;
    for (int s = 0; s < 8; s++) {
        float acc[4] = {0.f, 0.f, 0.f, 0.f};
        int rowb = bh*TT + t0 + s*16;
        #pragma unroll 4
        for (int m4 = 0; m4 < 64; m4++) {
            float4 kv4 = *(const float4*)&kvT[dl*QKV_PITCH + m4*4];
            #pragma unroll
            for (int r = 0; r < 4; r++) {
                float4 q4 = *(const float4*)&g_qp[(size_t)(rowb + rg + r*4)*MM + m4*4];
                acc[r] = fmaf(q4.x, kv4.x, acc[r]);
                acc[r] = fmaf(q4.y, kv4.y, acc[r]);
                acc[r] = fmaf(q4.z, kv4.z, acc[r]);
                acc[r] = fmaf(q4.w, kv4.w, acc[r]);
            }
        }
        #pragma unroll
        for (int r = 0; r < 4; r++)
            g_qkv[(size_t)(rowb + rg + r*4)*EE + dl] = acc[r];
    }
}

// ---------------- K11: qk1 = q_prime . ksum ----------------
__global__ void k_qk1ker() {
    int w = threadIdx.x >> 5, lane = threadIdx.x & 31;
    int row = blockIdx.x * 8 + w;
    int bh = row >> 12;
    const float* qp = g_qp + (size_t)row*MM;
    const float* ks = g_ksum + bh*MM;
    float a = 0.f;
    for (int m = lane; m < MM; m += 32) a = fmaf(qp[m], ks[m], a);
    #pragma unroll
    for (int m = 16; m > 0; m >>= 1) a += __shfl_xor_sync(0xffffffffu, a, m);
    if (lane == 0) g_qk1[row] = a;
}

// ---------------- K12: per-bucket attention, v2 ----------------
// smem float layout (25728 floats = 102912 B):
//  bufA [0, 8192)     : e-major swizzled q tile / qp chunks  [64 e][128 r]
//  bufB [8192, 16384) : e-major swizzled k tile / kp chunks
//  dots overlays [0, 16384): 128 rows x 128, pitch 128
//  sv   [16384, 25088): row-major 128 x pitch 68
//  qi 25088, ki 25216, qb 25344, kb 25472, pls 25600  (+128 each)
__global__ void __launch_bounds__(512, 1) k_bucket() {
    extern __shared__ float sm[];
    float* bufA = sm;
    float* bufB = sm + 8192;
    float* dots = sm;                       // pitch 128, overlays bufA+bufB
    float* sv   = sm + 16384;               // pitch 68
    int*      qi = (int*)(sm + 25088);
    int*      ki = (int*)(sm + 25216);
    unsigned* qb = (unsigned*)(sm + 25344);
    unsigned* kb = (unsigned*)(sm + 25472);
    float*   pls = sm + 25600;

    int tid = threadIdx.x;
    int n  = blockIdx.x & 31;
    int bh = (blockIdx.x >> 5) & 15;
    int h  = blockIdx.x >> 9;
    int hb = h * BHN + bh;

    if (tid < 128) qi[tid] = g_qpos[hb*TT + n*128 + tid];
    else if (tid < 256) ki[tid-128] = g_kpos[hb*TT + n*128 + (tid-128)];
    __syncthreads();

    // load q,k (swizzled transposed) and v (row-major), plus bucket ids
    for (int idx = tid; idx < 128*16; idx += 512) {
        int r = idx >> 4, e4 = idx & 15;
        int qrow = bh*TT + qi[r], krow = bh*TT + ki[r];
        float4 a = *(const float4*)&g_q[qrow*EE + e4*4];
        float4 b = *(const float4*)&g_k[krow*EE + e4*4];
        float4 c = *(const float4*)&g_v[krow*EE + e4*4];
        int r4 = r >> 2, rl = r & 3;
        #pragma unroll
        for (int u = 0; u < 4; u++) {
            int e = e4*4 + u;
            bufA[e*128 + swz(e, r4) + rl] = ((const float*)&a)[u];
            bufB[e*128 + swz(e, r4) + rl] = ((const float*)&b)[u];
        }
        *(float4*)&sv[r*68 + e4*4] = c;
    }
    if (tid < 128) {
        int q0 = qi[tid];
        unsigned pb = 0;
        #pragma unroll
        for (int hh = 0; hh < NHSH; hh++)
            pb |= ((unsigned)(g_qrev[(hh*BHN+bh)*TT + q0] >> 7)) << (8*hh);
        qb[tid] = pb;
        pls[tid] = g_qls[bh*TT + q0] + g_kls[bh];
    } else if (tid < 256) {
        int j = tid - 128;
        int k0 = ki[j];
        unsigned pb = 0;
        #pragma unroll
        for (int hh = 0; hh < NHSH; hh++)
            pb |= ((unsigned)(g_krev[(hh*BHN+bh)*TT + k0] >> 7)) << (8*hh);
        kb[j] = pb;
    }
    __syncthreads();

    int tx = tid & 15, ty = tid >> 4;   // rows ty*4+i, cols tx*8+j
    float accI[4][8], accP[4][8];
    #pragma unroll
    for (int i = 0; i < 4; i++)
        #pragma unroll
        for (int j = 0; j < 8; j++) { accI[i][j] = 0.f; accP[i][j] = 0.f; }

    // inner = s_q @ s_k^T (K=64)
    #pragma unroll 2
    for (int e = 0; e < 64; e++) {
        float4 a4  = *(const float4*)&bufA[e*128 + swz(e, ty)];
        float4 b4a = *(const float4*)&bufB[e*128 + swz(e, 2*tx)];
        float4 b4b = *(const float4*)&bufB[e*128 + swz(e, 2*tx+1)];
        const float* av = (const float*)&a4;
        const float* bv0 = (const float*)&b4a;
        const float* bv1 = (const float*)&b4b;
        #pragma unroll
        for (int i = 0; i < 4; i++) {
            #pragma unroll
            for (int j = 0; j < 4; j++) {
                accI[i][j]   = fmaf(av[i], bv0[j], accI[i][j]);
                accI[i][j+4] = fmaf(av[i], bv1[j], accI[i][j+4]);
            }
        }
    }
    __syncthreads();

    // dots_prime = sq_p @ sk_p^T (K=256, 4 chunks of 64 reusing bufA/bufB)
    for (int c = 0; c < 4; c++) {
        for (int idx = tid; idx < 128*16; idx += 512) {
            int r = idx >> 4, e4 = idx & 15;
            float4 a = *(const float4*)&g_qp[((size_t)(bh*TT+qi[r]))*MM + c*64 + e4*4];
            float4 b = *(const float4*)&g_kp[((size_t)(bh*TT+ki[r]))*MM + c*64 + e4*4];
            int r4 = r >> 2, rl = r & 3;
            #pragma unroll
            for (int u = 0; u < 4; u++) {
                int e = e4*4 + u;
                bufA[e*128 + swz(e, r4) + rl] = ((const float*)&a)[u];
                bufB[e*128 + swz(e, r4) + rl] = ((const float*)&b)[u];
            }
        }
        __syncthreads();
        #pragma unroll 2
        for (int e = 0; e < 64; e++) {
            float4 a4  = *(const float4*)&bufA[e*128 + swz(e, ty)];
            float4 b4a = *(const float4*)&bufB[e*128 + swz(e, 2*tx)];
            float4 b4b = *(const float4*)&bufB[e*128 + swz(e, 2*tx+1)];
            const float* av = (const float*)&a4;
            const float* bv0 = (const float*)&b4a;
            const float* bv1 = (const float*)&b4b;
            #pragma unroll
            for (int i = 0; i < 4; i++) {
                #pragma unroll
                for (int j = 0; j < 4; j++) {
                    accP[i][j]   = fmaf(av[i], bv0[j], accP[i][j]);
                    accP[i][j+4] = fmaf(av[i], bv1[j], accP[i][j+4]);
                }
            }
        }
        __syncthreads();
    }

    // duplicate-count correction + per-row lse + dots (overlays bufA/bufB)
    const float LOGT[5] = {0.f, 0.f, 0.69314718056f, 1.09861228867f, 1.38629436112f};
    const float RCPT[5] = {1.f, 1.f, 0.5f, 0.33333333333f, 0.25f};
    unsigned qb_r[4], kb_c[8];
    float plsr[4], rowm[4];
    #pragma unroll
    for (int i = 0; i < 4; i++) {
        qb_r[i] = qb[ty*4+i]; plsr[i] = pls[ty*4+i]; rowm[i] = -3.402823466e38f;
    }
    #pragma unroll
    for (int j = 0; j < 8; j++) kb_c[j] = kb[tx*8+j];

    #pragma unroll
    for (int i = 0; i < 4; i++)
        #pragma unroll
        for (int j = 0; j < 8; j++) {
            int cnt = __popc(__vcmpeq4(qb_r[i], kb_c[j])) >> 3;
            float inner = accI[i][j] * TEMP - LOGT[cnt];
            accI[i][j] = inner;
            accP[i][j] *= RCPT[cnt];
            rowm[i] = fmaxf(rowm[i], inner);
        }
    #pragma unroll
    for (int i = 0; i < 4; i++)
        #pragma unroll
        for (int m = 8; m >= 1; m >>= 1)
            rowm[i] = fmaxf(rowm[i], __shfl_xor_sync(0xffffffffu, rowm[i], m));

    #pragma unroll
    for (int i = 0; i < 4; i++) {
        float l = fmaxf(rowm[i], plsr[i]);
        float e2 = expf(plsr[i] - l);
        float s = 0.f;
        float dv[8];
        #pragma unroll
        for (int j = 0; j < 8; j++) {
            float d = expf(accI[i][j] - l) - accP[i][j] * e2;
            s += d;
            dv[j] = d;
        }
        *(float4*)&dots[(ty*4+i)*128 + tx*8]     = make_float4(dv[0], dv[1], dv[2], dv[3]);
        *(float4*)&dots[(ty*4+i)*128 + tx*8 + 4] = make_float4(dv[4], dv[5], dv[6], dv[7]);
        #pragma unroll
        for (int m = 8; m >= 1; m >>= 1) s += __shfl_xor_sync(0xffffffffu, s, m);
        if (tx == 0) {
            int q0 = qi[ty*4+i];
            g_logits[hb*TT + q0] = l;
            g_dsum[hb*TT + q0]   = s;
        }
    }
    __syncthreads();

    // epilogue: so = dots @ s_v ; thread = 4 rows x 4 cols
    int cx = tid & 15, ry = tid >> 4;
    float acc2[4][4];
    #pragma unroll
    for (int i = 0; i < 4; i++)
        #pragma unroll
        for (int dd = 0; dd < 4; dd++) acc2[i][dd] = 0.f;
    #pragma unroll 4
    for (int j = 0; j < 128; j++) {
        float4 v4 = *(const float4*)&sv[j*68 + cx*4];
        #pragma unroll
        for (int i = 0; i < 4; i++) {
            float dij = dots[(ry*4+i)*128 + j];
            acc2[i][0] = fmaf(dij, v4.x, acc2[i][0]);
            acc2[i][1] = fmaf(dij, v4.y, acc2[i][1]);
            acc2[i][2] = fmaf(dij, v4.z, acc2[i][2]);
            acc2[i][3] = fmaf(dij, v4.w, acc2[i][3]);
        }
    }
    #pragma unroll
    for (int i = 0; i < 4; i++) {
        int q0 = qi[ry*4+i];
        *(float4*)&g_o[((size_t)(hb*TT + q0))*EE + cx*4] =
            make_float4(acc2[i][0], acc2[i][1], acc2[i][2], acc2[i][3]);
    }
}

// ---------------- K13: combine across hashes + global correction ----------------
__global__ void k_combine(float* __restrict__ out) {
    int tid = threadIdx.x;
    int row = blockIdx.x * 4 + (tid >> 6);
    int d = tid & 63;
    int bh = row >> 12, t = row & 4095;
    float l[NHSH];
    #pragma unroll
    for (int h = 0; h < NHSH; h++) l[h] = g_logits[(h*BHN+bh)*TT + t];
    float mx = fmaxf(fmaxf(l[0], l[1]), fmaxf(l[2], l[3]));
    float se = 0.f;
    #pragma unroll
    for (int h = 0; h < NHSH; h++) se += expf(l[h] - mx);
    float nls = mx + logf(se);
    float o = 0.f, nr = 0.f;
    #pragma unroll
    for (int h = 0; h < NHSH; h++) {
        float p = expf(l[h] - nls);
        o  = fmaf(g_o[((size_t)((h*BHN+bh)*TT + t))*EE + d], p, o);
        nr = fmaf(g_dsum[(h*BHN+bh)*TT + t], p, nr);
    }
    float ps = expf(g_qls[row] + g_kls[bh] - nls);
    o  = fmaf(g_qkv[row*EE+d], ps, o);
    nr = fmaf(g_qk1[row], ps, nr);
    o /= fmaxf(nr, 1e-6f);
    int b = bh >> 3, hh = bh & 7;
    out[((b*TT + t)*HH + hh)*EE + d] = o;
}

// ---------------- launch ----------------
extern "C" void kernel_launch(void* const* d_in, const int* in_sizes, int n_in,
                              void* d_out, int out_size) {
    const float* q     = (const float*)d_in[0];
    const float* k     = (const float*)d_in[1];
    const float* v     = (const float*)d_in[2];
    const float* proj  = (const float*)d_in[3];
    const float* alpha = (const float*)d_in[4];
    const float* beta  = (const float*)d_in[5];
    float* out = (float*)d_out;

    cudaFuncSetAttribute(k_feats_q, cudaFuncAttributeMaxDynamicSharedMemorySize, (64+9)*4);
    cudaFuncSetAttribute(k_feats_k, cudaFuncAttributeMaxDynamicSharedMemorySize, (64+9)*4);
    cudaFuncSetAttribute(k_qkvker,  cudaFuncAttributeMaxDynamicSharedMemorySize, 64*QKV_PITCH*4);
    cudaFuncSetAttribute(k_bucket,  cudaFuncAttributeMaxDynamicSharedMemorySize, 25728*4);

    k_transpose<<<BHT/4, 256>>>(q, k, v);
    k_maxnorm<<<BHN, 256>>>();
    k_hash<<<BHT/8, 256>>>(alpha, beta);
    k_sort<<<2*NHSH*BHN, 512>>>();
    k_feats_q<<<BHT/16, 256, (64+9)*4>>>(proj);
    k_feats_k<<<BHT/16, 256, (64+9)*4>>>(proj);
    k_kls<<<BHN, 256>>>();
    k_kexp<<<(BHT*MM/4)/256, 256>>>();
    k_zero<<<(BHN*MM*EE + 255)/256, 256>>>();
    k_kvker<<<dim3(TT/128, BHN), 256>>>();
    k_qkvker<<<BHN*32, 256, 64*QKV_PITCH*4>>>();
    k_qk1ker<<<BHT/8, 256>>>();
    k_bucket<<<NHSH*BHN*NB, 512, 25728*4>>>();
    k_combine<<<BHT/4, 256>>>(out);
}